// round 9
// baseline (speedup 1.0000x reference)
#include <cuda_runtime.h>
#include <cuda_bf16.h>
#include <cstdint>

#define EMBED 2048
#define HD    128
#define NB    4
#define SEQ   2048

// ---------------------------------------------------------------------------
// Scratch globals (all tf32-rounded fp32)
// ---------------------------------------------------------------------------
__device__ __align__(16) float g_x [(size_t)NB * SEQ * EMBED];  // rna-tf32 [row][k]
__device__ __align__(16) float g_Wt[3 * HD * EMBED];            // rna-tf32 [w][n][k]
__device__ __align__(16) float g_q [NB * SEQ * HD];             // [b][s][d]
__device__ __align__(16) float g_k [NB * SEQ * HD];             // [b][s][d]
__device__ __align__(16) float g_vt[NB * HD * SEQ];             // [b][d][s]

__device__ __forceinline__ uint32_t smem_u32(const void* p) {
    uint32_t a;
    asm("{ .reg .u64 t; cvta.to.shared.u64 t, %1; cvt.u32.u64 %0, t; }"
        : "=r"(a) : "l"(p));
    return a;
}
__device__ __forceinline__ float tf32rna(float x) {
    uint32_t r;
    asm("cvt.rna.tf32.f32 %0, %1;" : "=r"(r) : "f"(x));
    return __uint_as_float(r);
}
// tf32 m16n8k8 (fragments loaded via b16 ldmatrix on fp32 data)
__device__ __forceinline__ void mma1688t(float* c, const uint32_t* a,
                                         const uint32_t* b) {
    asm volatile(
        "mma.sync.aligned.m16n8k8.row.col.f32.tf32.tf32.f32 "
        "{%0,%1,%2,%3}, {%4,%5,%6,%7}, {%8,%9}, {%0,%1,%2,%3};"
        : "+f"(c[0]), "+f"(c[1]), "+f"(c[2]), "+f"(c[3])
        : "r"(a[0]), "r"(a[1]), "r"(a[2]), "r"(a[3]), "r"(b[0]), "r"(b[1]));
}
__device__ __forceinline__ void ldsm4(uint32_t* r, uint32_t saddr) {
    asm volatile("ldmatrix.sync.aligned.m8n8.x4.shared.b16 {%0,%1,%2,%3}, [%4];"
                 : "=r"(r[0]), "=r"(r[1]), "=r"(r[2]), "=r"(r[3]) : "r"(saddr));
}
__device__ __forceinline__ void cpa16(uint32_t dst, const void* src) {
    asm volatile("cp.async.cg.shared.global [%0], [%1], 16;"
                 :: "r"(dst), "l"(__cvta_generic_to_global(src)) : "memory");
}
#define CP_COMMIT() asm volatile("cp.async.commit_group;" ::: "memory")
#define CP_WAIT1()  asm volatile("cp.async.wait_group 1;" ::: "memory")

// ---------------------------------------------------------------------------
// prep3 (unchanged, passing): W -> [w][n][k] rna-tf32; X -> rna-tf32
// ---------------------------------------------------------------------------
__global__ __launch_bounds__(256)
void prep3(const float* __restrict__ X,
           const float* __restrict__ Wq, const float* __restrict__ Wk,
           const float* __restrict__ Wv)
{
    const int t = threadIdx.x;
    if (blockIdx.x < 48) {
        __shared__ float Ws[128][132];
        const int w  = blockIdx.x >> 4;
        const int k0 = (blockIdx.x & 15) * 128;
        const float* __restrict__ W = (w == 0) ? Wq : (w == 1 ? Wk : Wv);

        for (int l = 0; l < 64; ++l) {
            int idx = t + l * 256;
            int kk = idx >> 7, n = idx & 127;
            Ws[kk][n] = W[(size_t)(k0 + kk) * HD + n];
        }
        __syncthreads();

        const int n = t >> 1, kh = (t & 1) * 64;
        float* dst = g_Wt + (size_t)w * HD * EMBED + (size_t)n * EMBED + k0 + kh;
        #pragma unroll
        for (int g = 0; g < 16; ++g) {
            float4 v = make_float4(tf32rna(Ws[kh + g * 4 + 0][n]),
                                   tf32rna(Ws[kh + g * 4 + 1][n]),
                                   tf32rna(Ws[kh + g * 4 + 2][n]),
                                   tf32rna(Ws[kh + g * 4 + 3][n]));
            *(float4*)(dst + g * 4) = v;
        }
    } else {
        const size_t N4 = (size_t)NB * SEQ * EMBED / 4;
        const size_t nthr = 976 * 256;
        size_t c = (size_t)(blockIdx.x - 48) * 256 + t;
        for (; c < N4; c += nthr) {
            float4 v = *(const float4*)(X + c * 4);
            v.x = tf32rna(v.x); v.y = tf32rna(v.y);
            v.z = tf32rna(v.z); v.w = tf32rna(v.w);
            *(float4*)(g_x + c * 4) = v;
        }
    }
}

// ---------------------------------------------------------------------------
// qkv3: single-term TF32 GEMM (passing R8 mainloop); epilogue now emits
// tf32-rounded fp32: q,k [b][s][d]; v transposed [b][d][s].
// ---------------------------------------------------------------------------
#define KC    32
#define LDW   36
#define LDW16 72
#define A3STG (64 * LDW * 4)
#define B3STG (128 * LDW * 4)
#define O3_A  0
#define O3_B  (2 * A3STG)
#define O3_BIAS (O3_B + 2 * B3STG)
#define QSM3_TOTAL (O3_BIAS + 512)

__global__ __launch_bounds__(256, 3)
void qkv3(const float* __restrict__ bq, const float* __restrict__ bk,
          const float* __restrict__ bv)
{
    extern __shared__ char smem[];
    const uint32_t sb = smem_u32(smem);
    float* biasS = (float*)(smem + O3_BIAS);

    const int wsel = blockIdx.y;
    const int m0   = blockIdx.x * 64;
    const int t    = threadIdx.x;
    const int wid  = t >> 5, lane = t & 31;
    const int g    = lane >> 2, tig = lane & 3;
    const int wm   = wid >> 2, wn = wid & 3;

    const int aiA = (((lane >> 3) & 1) * 8 + (lane & 7)) * LDW16 + (lane >> 4) * 8;
    const int biB = ((lane >> 4) * 8 + (lane & 7)) * LDW16 + ((lane >> 3) & 1) * 8;

    if (t < 128) {
        const float* bias = (wsel == 0) ? bq : (wsel == 1 ? bk : bv);
        biasS[t] = bias[t];
    }

    const float* Wt = g_Wt + (size_t)wsel * HD * EMBED;
    const int ar = t >> 2, ac = t & 3;
    const int br = t >> 1, bh = t & 1;

    float c[2][4][4];
    #pragma unroll
    for (int i = 0; i < 2; ++i)
        #pragma unroll
        for (int j = 0; j < 4; ++j)
            #pragma unroll
            for (int q = 0; q < 4; ++q) c[i][j][q] = 0.f;

    #pragma unroll
    for (int pi = 0; pi < 2; ++pi) {
        const int kb = pi * KC;
        {
            const float* src = g_x + (size_t)(m0 + ar) * EMBED + kb + ac * 8;
            const uint32_t dst = sb + O3_A + pi * A3STG + ar * (LDW * 4) + ac * 32;
            cpa16(dst, src);
            cpa16(dst + 16, src + 4);
        }
        {
            const float* src = Wt + (size_t)br * EMBED + kb + bh * 16;
            const uint32_t dst = sb + O3_B + pi * B3STG + br * (LDW * 4) + bh * 64;
            #pragma unroll
            for (int j = 0; j < 4; ++j) cpa16(dst + j * 16, src + j * 4);
        }
        CP_COMMIT();
    }

    for (int kt = 0; kt < EMBED / KC; ++kt) {
        const int st = kt & 1;
        const uint32_t sA = sb + O3_A + st * A3STG;
        const uint32_t sB = sb + O3_B + st * B3STG;

        CP_WAIT1();
        __syncthreads();

        #pragma unroll
        for (int ks = 0; ks < 4; ++ks) {
            const int ko = ks * 16;
            uint32_t a[2][4], bb[2][4];
            #pragma unroll
            for (int mi = 0; mi < 2; ++mi)
                ldsm4(a[mi], sA + 2 * ((wm * 32 + mi * 16) * LDW16 + ko + aiA));
            #pragma unroll
            for (int h = 0; h < 2; ++h)
                ldsm4(bb[h], sB + 2 * ((wn * 32 + h * 16) * LDW16 + ko + biB));
            #pragma unroll
            for (int mi = 0; mi < 2; ++mi)
                #pragma unroll
                for (int nt = 0; nt < 4; ++nt)
                    mma1688t(c[mi][nt], a[mi], &bb[nt >> 1][(nt & 1) * 2]);
        }
        __syncthreads();

        if (kt + 2 < EMBED / KC) {
            const int kb = (kt + 2) * KC;
            {
                const float* src = g_x + (size_t)(m0 + ar) * EMBED + kb + ac * 8;
                const uint32_t dst = sb + O3_A + st * A3STG + ar * (LDW * 4) + ac * 32;
                cpa16(dst, src);
                cpa16(dst + 16, src + 4);
            }
            {
                const float* src = Wt + (size_t)br * EMBED + kb + bh * 16;
                const uint32_t dst = sb + O3_B + st * B3STG + br * (LDW * 4) + bh * 64;
                #pragma unroll
                for (int j = 0; j < 4; ++j) cpa16(dst + j * 16, src + j * 4);
            }
        }
        CP_COMMIT();
    }

    // ---- epilogue: frags (+bias) -> Ct -> tf32-rounded fp32 gmem
    __syncthreads();
    float (*Ct)[132] = (float (*)[132])smem;
    #pragma unroll
    for (int mi = 0; mi < 2; ++mi) {
        const int r = wm * 32 + mi * 16 + g;
        #pragma unroll
        for (int nt = 0; nt < 4; ++nt) {
            const int n = wn * 32 + nt * 8 + tig * 2;
            Ct[r][n]         = c[mi][nt][0] + biasS[n];
            Ct[r][n + 1]     = c[mi][nt][1] + biasS[n + 1];
            Ct[r + 8][n]     = c[mi][nt][2] + biasS[n];
            Ct[r + 8][n + 1] = c[mi][nt][3] + biasS[n + 1];
        }
    }
    __syncthreads();

    const int batch = m0 >> 11, s0 = m0 & 2047;
    if (wsel < 2) {
        const int r = t >> 2, dq = (t & 3) * 32;
        float* dst = (wsel == 0 ? g_q : g_k)
            + ((size_t)batch * SEQ + s0 + r) * HD + dq;
        #pragma unroll
        for (int qq = 0; qq < 8; ++qq) {
            float4 v = make_float4(tf32rna(Ct[r][dq + qq * 4 + 0]),
                                   tf32rna(Ct[r][dq + qq * 4 + 1]),
                                   tf32rna(Ct[r][dq + qq * 4 + 2]),
                                   tf32rna(Ct[r][dq + qq * 4 + 3]));
            *(float4*)(dst + qq * 4) = v;
        }
    } else {
        const int d = t >> 1, sch = (t & 1) * 32;
        float* dst = g_vt + ((size_t)batch * HD + d) * SEQ + s0 + sch;
        #pragma unroll
        for (int qq = 0; qq < 8; ++qq) {
            float4 v = make_float4(tf32rna(Ct[sch + qq * 4 + 0][d]),
                                   tf32rna(Ct[sch + qq * 4 + 1][d]),
                                   tf32rna(Ct[sch + qq * 4 + 2][d]),
                                   tf32rna(Ct[sch + qq * 4 + 3][d]));
            *(float4*)(dst + qq * 4) = v;
        }
    }
}

// ---------------------------------------------------------------------------
// attn5: single-term TF32 flash attention, cp.async 2-stage pipeline,
// balanced causal pairing. grid (32, 4); CTA x does q-tiles {x, 63-x}.
// Per iter per warp: QK 16 k8-steps x 2 MMA = 32; PV 8 k8-steps x 4 = 32.
// ---------------------------------------------------------------------------
#define KT    64
#define LDQ   132          // fp32 stride for Q/K rows (128 + 4 pad)
#define LDQ16 264
#define LDV   68           // fp32 stride for V/P rows (64 + 4 pad)
#define LDV16 136

#define A5_Q   0                              // 32*132*4  = 16896
#define A5_K   16896                          // 2 * 33792
#define A5_V   (16896 + 2 * 33792)            // 84480; 2 * 34816
#define A5_PS  (84480 + 2 * 34816)            // 154112; 32*68*4 = 8704
#define A5_MLA (154112 + 8704)                // 162816
#define ASM5_TOTAL (162816 + 384)             // 163200
#define KSTG 33792
#define VSTG 34816

__global__ __launch_bounds__(256)
void attn5(float* __restrict__ out)
{
    extern __shared__ char smem[];
    const uint32_t sb = smem_u32(smem);
    float* Ps   = (float*)(smem + A5_PS);
    float* m_s  = (float*)(smem + A5_MLA);
    float* l_s  = m_s + 32;
    float* al_s = l_s + 32;

    const int b = blockIdx.y, t = threadIdx.x;
    const int wid = t >> 5, lane = t & 31;
    const int g = lane >> 2, tig = lane & 3;
    const int wm = wid & 1, wn = wid >> 1;

    const int aiQ = (((lane >> 3) & 1) * 8 + (lane & 7)) * LDQ16 + (lane >> 4) * 8;
    const int biK = ((lane >> 4) * 8 + (lane & 7)) * LDQ16 + ((lane >> 3) & 1) * 8;
    const int aiP = (((lane >> 3) & 1) * 8 + (lane & 7)) * LDV16 + (lane >> 4) * 8;
    const int biV = ((lane >> 4) * 8 + (lane & 7)) * LDV16 + ((lane >> 3) & 1) * 8;

    const float* gQ  = g_q  + (size_t)b * SEQ * HD;
    const float* gK  = g_k  + (size_t)b * SEQ * HD;
    const float* gVt = g_vt + (size_t)b * HD * SEQ;

    const float RSC = 0.08838834764831845f;
    const int sr = t >> 3, sc0 = (t & 7) * 8;
    const int kr = t >> 2, kc = t & 3;     // K cp.async: row, 32-fp32 chunk
    const int vr = t >> 1, vh = t & 1;     // V cp.async: d-row, 32-fp32 half

    for (int subt = 0; subt < 2; ++subt) {
        const int jt = subt ? (63 - blockIdx.x) : blockIdx.x;
        const int q0 = jt * 32;
        const int iters = (jt >> 1) + 1;

        // Q tile: 32 rows x 128 fp32
        {
            const int r = t >> 3, dq = (t & 7) * 16;
            const float* src = gQ + (size_t)(q0 + r) * HD + dq;
            float* dst = (float*)(smem + A5_Q) + r * LDQ + dq;
            #pragma unroll
            for (int j = 0; j < 4; ++j)
                *(float4*)(dst + j * 4) = *(const float4*)(src + j * 4);
        }
        if (t < 32) { m_s[t] = -1e30f; l_s[t] = 0.f; }

        float o[4][4];
        #pragma unroll
        for (int nt = 0; nt < 4; ++nt)
            #pragma unroll
            for (int q = 0; q < 4; ++q) o[nt][q] = 0.f;

        // prologue: stages 0,1
        #pragma unroll
        for (int pi = 0; pi < 2; ++pi) {
            if (pi < iters) {
                const int k0 = pi * KT;
                {
                    const float* src = gK + (size_t)(k0 + kr) * HD + kc * 32;
                    const uint32_t dst = sb + A5_K + pi * KSTG + kr * (LDQ * 4) + kc * 128;
                    #pragma unroll
                    for (int j = 0; j < 8; ++j) cpa16(dst + j * 16, src + j * 4);
                }
                {
                    const float* src = gVt + (size_t)vr * SEQ + k0 + vh * 32;
                    const uint32_t dst = sb + A5_V + pi * VSTG + vr * (LDV * 4) + vh * 128;
                    #pragma unroll
                    for (int j = 0; j < 8; ++j) cpa16(dst + j * 16, src + j * 4);
                }
            }
            CP_COMMIT();
        }

        for (int it = 0; it < iters; ++it) {
            const int k0 = it * KT;
            const int st = it & 1;
            const uint32_t sK = sb + A5_K + st * KSTG;
            const uint32_t sV = sb + A5_V + st * VSTG;

            CP_WAIT1();
            __syncthreads();

            // ---- QK^T: S(32x64) tf32; warp tile 16x16
            float s4[2][4];
            #pragma unroll
            for (int nt = 0; nt < 2; ++nt)
                #pragma unroll
                for (int q = 0; q < 4; ++q) s4[nt][q] = 0.f;
            #pragma unroll
            for (int ks = 0; ks < 16; ++ks) {
                const int ko = ks * 16;     // b16 units = 8 fp32
                uint32_t qa[4], kb4[4];
                ldsm4(qa,  sb + A5_Q + 2 * (wm * 16 * LDQ16 + ko + aiQ));
                ldsm4(kb4, sK + 2 * (wn * 16 * LDQ16 + ko + biK));
                mma1688t(s4[0], qa, &kb4[0]);
                mma1688t(s4[1], qa, &kb4[2]);
            }
            {
                const int row0 = wm * 16 + g;
                #pragma unroll
                for (int nt = 0; nt < 2; ++nt) {
                    const int col = wn * 16 + nt * 8 + tig * 2;
                    *(float2*)&Ps[row0 * LDV + col] = make_float2(s4[nt][0], s4[nt][1]);
                    *(float2*)&Ps[(row0 + 8) * LDV + col] = make_float2(s4[nt][2], s4[nt][3]);
                }
            }
            __syncthreads();

            // ---- softmax (fp32); write tf32-rounded P in place
            {
                const int gq = q0 + sr;
                float sv[8];
                float rm = -1e30f;
                #pragma unroll
                for (int j = 0; j < 8; ++j) {
                    float v = Ps[sr * LDV + sc0 + j] * RSC;
                    if (k0 + sc0 + j > gq) v = -1e10f;
                    sv[j] = v;
                    rm = fmaxf(rm, v);
                }
                #pragma unroll
                for (int off = 4; off >= 1; off >>= 1)
                    rm = fmaxf(rm, __shfl_xor_sync(0xffffffffu, rm, off));
                const float mo = m_s[sr];
                const float mn = fmaxf(mo, rm);
                float rs = 0.f;
                float pv[8];
                #pragma unroll
                for (int j = 0; j < 8; ++j) {
                    float p = __expf(sv[j] - mn);
                    rs += p;
                    pv[j] = tf32rna(p);
                }
                #pragma unroll
                for (int off = 4; off >= 1; off >>= 1)
                    rs += __shfl_xor_sync(0xffffffffu, rs, off);
                *(float4*)&Ps[sr * LDV + sc0] =
                    make_float4(pv[0], pv[1], pv[2], pv[3]);
                *(float4*)&Ps[sr * LDV + sc0 + 4] =
                    make_float4(pv[4], pv[5], pv[6], pv[7]);
                if ((t & 7) == 0) {
                    const float al = __expf(mo - mn);
                    m_s[sr]  = mn;
                    al_s[sr] = al;
                    l_s[sr]  = l_s[sr] * al + rs;
                }
            }
            __syncthreads();

            // ---- PV: O = alpha*O + P V ; warp tile 16 rows x 32 d
            {
                const float a0 = al_s[wm * 16 + g];
                const float a1 = al_s[wm * 16 + g + 8];
                #pragma unroll
                for (int nt = 0; nt < 4; ++nt) {
                    o[nt][0] *= a0; o[nt][1] *= a0;
                    o[nt][2] *= a1; o[nt][3] *= a1;
                }
                #pragma unroll
                for (int ks = 0; ks < 8; ++ks) {
                    const int ko = ks * 16;
                    uint32_t pa[4], vb[2][4];
                    ldsm4(pa, sb + A5_PS + 2 * (wm * 16 * LDV16 + ko + aiP));
                    #pragma unroll
                    for (int h = 0; h < 2; ++h)
                        ldsm4(vb[h], sV + 2 * ((wn * 32 + h * 16) * LDV16 + ko + biV));
                    #pragma unroll
                    for (int nt = 0; nt < 4; ++nt)
                        mma1688t(o[nt], pa, &vb[nt >> 1][(nt & 1) * 2]);
                }
            }
            __syncthreads();

            // ---- prefetch it+2 into stage st
            if (it + 2 < iters) {
                const int kn = (it + 2) * KT;
                {
                    const float* src = gK + (size_t)(kn + kr) * HD + kc * 32;
                    const uint32_t dst = sb + A5_K + st * KSTG + kr * (LDQ * 4) + kc * 128;
                    #pragma unroll
                    for (int j = 0; j < 8; ++j) cpa16(dst + j * 16, src + j * 4);
                }
                {
                    const float* src = gVt + (size_t)vr * SEQ + kn + vh * 32;
                    const uint32_t dst = sb + A5_V + st * VSTG + vr * (LDV * 4) + vh * 128;
                    #pragma unroll
                    for (int j = 0; j < 8; ++j) cpa16(dst + j * 16, src + j * 4);
                }
            }
            CP_COMMIT();
        }

        // ---- epilogue
        {
            const float li0 = 1.f / l_s[wm * 16 + g];
            const float li1 = 1.f / l_s[wm * 16 + g + 8];
            float* op0 = out + ((size_t)b * SEQ + q0 + wm * 16 + g) * HD;
            float* op1 = op0 + 8 * HD;
            #pragma unroll
            for (int nt = 0; nt < 4; ++nt) {
                const int d = wn * 32 + nt * 8 + tig * 2;
                *(float2*)(op0 + d) = make_float2(o[nt][0] * li0, o[nt][1] * li0);
                *(float2*)(op1 + d) = make_float2(o[nt][2] * li1, o[nt][3] * li1);
            }
        }
        __syncthreads();   // before subt=1 reuses Q/stats/smem
    }
}

// ---------------------------------------------------------------------------
extern "C" void kernel_launch(void* const* d_in, const int* in_sizes, int n_in,
                              void* d_out, int out_size)
{
    const float* X  = (const float*)d_in[0];
    const float* Wq = (const float*)d_in[1];
    const float* bq = (const float*)d_in[2];
    const float* Wk = (const float*)d_in[3];
    const float* bk = (const float*)d_in[4];
    const float* Wv = (const float*)d_in[5];
    const float* bv = (const float*)d_in[6];
    float* out = (float*)d_out;

    prep3<<<1024, 256>>>(X, Wq, Wk, Wv);

    cudaFuncSetAttribute(qkv3, cudaFuncAttributeMaxDynamicSharedMemorySize,
                         QSM3_TOTAL);
    qkv3<<<dim3(128, 3), 256, QSM3_TOTAL>>>(bq, bk, bv);

    cudaFuncSetAttribute(attn5, cudaFuncAttributeMaxDynamicSharedMemorySize,
                         ASM5_TOTAL);
    attn5<<<dim3(32, 4), 256, ASM5_TOTAL>>>(out);
}

// round 10
// speedup vs baseline: 1.1196x; 1.1196x over previous
#include <cuda_runtime.h>
#include <cuda_bf16.h>
#include <cstdint>

#define EMBED 2048
#define HD    128
#define NB    4
#define SEQ   2048

// ---------------------------------------------------------------------------
// Scratch globals
// ---------------------------------------------------------------------------
__device__ __align__(16) float g_Wt[3 * HD * EMBED];            // rna-tf32 [w][n][k]
__device__ __align__(16) __nv_bfloat16 g_qhi[NB * SEQ * HD];    // [b][s][d]
__device__ __align__(16) __nv_bfloat16 g_qlo[NB * SEQ * HD];
__device__ __align__(16) __nv_bfloat16 g_khi[NB * SEQ * HD];    // [b][s][d]
__device__ __align__(16) __nv_bfloat16 g_klo[NB * SEQ * HD];
__device__ __align__(16) __nv_bfloat16 g_vthi[NB * HD * SEQ];   // [b][d][s]
__device__ __align__(16) __nv_bfloat16 g_vtlo[NB * HD * SEQ];

__device__ __forceinline__ uint32_t pk2(__nv_bfloat16 a, __nv_bfloat16 b) {
    return ((uint32_t)__bfloat16_as_ushort(b) << 16) | __bfloat16_as_ushort(a);
}
__device__ __forceinline__ uint32_t smem_u32(const void* p) {
    uint32_t a;
    asm("{ .reg .u64 t; cvta.to.shared.u64 t, %1; cvt.u32.u64 %0, t; }"
        : "=r"(a) : "l"(p));
    return a;
}
__device__ __forceinline__ float tf32rna(float x) {
    uint32_t r;
    asm("cvt.rna.tf32.f32 %0, %1;" : "=r"(r) : "f"(x));
    return __uint_as_float(r);
}
// bf16 m16n8k16
__device__ __forceinline__ void mma16816(float* c, const uint32_t* a,
                                         const uint32_t* b) {
    asm volatile(
        "mma.sync.aligned.m16n8k16.row.col.f32.bf16.bf16.f32 "
        "{%0,%1,%2,%3}, {%4,%5,%6,%7}, {%8,%9}, {%0,%1,%2,%3};"
        : "+f"(c[0]), "+f"(c[1]), "+f"(c[2]), "+f"(c[3])
        : "r"(a[0]), "r"(a[1]), "r"(a[2]), "r"(a[3]), "r"(b[0]), "r"(b[1]));
}
// tf32 m16n8k8 (fragments via b16 ldmatrix on fp32 data; HW truncates to tf32)
__device__ __forceinline__ void mma1688t(float* c, const uint32_t* a,
                                         const uint32_t* b) {
    asm volatile(
        "mma.sync.aligned.m16n8k8.row.col.f32.tf32.tf32.f32 "
        "{%0,%1,%2,%3}, {%4,%5,%6,%7}, {%8,%9}, {%0,%1,%2,%3};"
        : "+f"(c[0]), "+f"(c[1]), "+f"(c[2]), "+f"(c[3])
        : "r"(a[0]), "r"(a[1]), "r"(a[2]), "r"(a[3]), "r"(b[0]), "r"(b[1]));
}
__device__ __forceinline__ void ldsm4(uint32_t* r, uint32_t saddr) {
    asm volatile("ldmatrix.sync.aligned.m8n8.x4.shared.b16 {%0,%1,%2,%3}, [%4];"
                 : "=r"(r[0]), "=r"(r[1]), "=r"(r[2]), "=r"(r[3]) : "r"(saddr));
}
__device__ __forceinline__ void cpa16(uint32_t dst, const void* src) {
    asm volatile("cp.async.cg.shared.global [%0], [%1], 16;"
                 :: "r"(dst), "l"(__cvta_generic_to_global(src)) : "memory");
}
#define CP_COMMIT() asm volatile("cp.async.commit_group;" ::: "memory")
#define CP_WAIT1()  asm volatile("cp.async.wait_group 1;" ::: "memory")

// ---------------------------------------------------------------------------
// prep_w48: W fp32 [k][n] -> rna-tf32 fp32 [w][n][k].  grid = 48.
// (X is consumed raw by qkv3 — tf32 MMA truncates fp32 bits in hardware.)
// ---------------------------------------------------------------------------
__global__ __launch_bounds__(256)
void prep_w48(const float* __restrict__ Wq, const float* __restrict__ Wk,
              const float* __restrict__ Wv)
{
    __shared__ float Ws[128][132];
    const int t = threadIdx.x;
    const int w  = blockIdx.x >> 4;
    const int k0 = (blockIdx.x & 15) * 128;
    const float* __restrict__ W = (w == 0) ? Wq : (w == 1 ? Wk : Wv);

    for (int l = 0; l < 64; ++l) {
        int idx = t + l * 256;
        int kk = idx >> 7, n = idx & 127;
        Ws[kk][n] = W[(size_t)(k0 + kk) * HD + n];
    }
    __syncthreads();

    const int n = t >> 1, kh = (t & 1) * 64;
    float* dst = g_Wt + (size_t)w * HD * EMBED + (size_t)n * EMBED + k0 + kh;
    #pragma unroll
    for (int g = 0; g < 16; ++g) {
        float4 v = make_float4(tf32rna(Ws[kh + g * 4 + 0][n]),
                               tf32rna(Ws[kh + g * 4 + 1][n]),
                               tf32rna(Ws[kh + g * 4 + 2][n]),
                               tf32rna(Ws[kh + g * 4 + 3][n]));
        *(float4*)(dst + g * 4) = v;
    }
}

// ---------------------------------------------------------------------------
// qkv3: single-term TF32 GEMM. M64 x N128 x K2048, grid (128, 3), 256 thr.
// A streamed straight from harness X (raw fp32); B from rna-tf32 W.
// Epilogue emits Q,K,V as bf16 hi/lo (for the bf16 3-term attention).
// ---------------------------------------------------------------------------
#define KC    32
#define LDW   36
#define LDW16 72
#define A3STG (64 * LDW * 4)
#define B3STG (128 * LDW * 4)
#define O3_A  0
#define O3_B  (2 * A3STG)
#define O3_BIAS (O3_B + 2 * B3STG)
#define QSM3_TOTAL (O3_BIAS + 512)

__global__ __launch_bounds__(256, 3)
void qkv3(const float* __restrict__ X,
          const float* __restrict__ bq, const float* __restrict__ bk,
          const float* __restrict__ bv)
{
    extern __shared__ char smem[];
    const uint32_t sb = smem_u32(smem);
    float* biasS = (float*)(smem + O3_BIAS);

    const int wsel = blockIdx.y;
    const int m0   = blockIdx.x * 64;
    const int t    = threadIdx.x;
    const int wid  = t >> 5, lane = t & 31;
    const int g    = lane >> 2, tig = lane & 3;
    const int wm   = wid >> 2, wn = wid & 3;

    const int aiA = (((lane >> 3) & 1) * 8 + (lane & 7)) * LDW16 + (lane >> 4) * 8;
    const int biB = ((lane >> 4) * 8 + (lane & 7)) * LDW16 + ((lane >> 3) & 1) * 8;

    if (t < 128) {
        const float* bias = (wsel == 0) ? bq : (wsel == 1 ? bk : bv);
        biasS[t] = bias[t];
    }

    const float* Wt = g_Wt + (size_t)wsel * HD * EMBED;
    const int ar = t >> 2, ac = t & 3;
    const int br = t >> 1, bh = t & 1;

    float c[2][4][4];
    #pragma unroll
    for (int i = 0; i < 2; ++i)
        #pragma unroll
        for (int j = 0; j < 4; ++j)
            #pragma unroll
            for (int q = 0; q < 4; ++q) c[i][j][q] = 0.f;

    #pragma unroll
    for (int pi = 0; pi < 2; ++pi) {
        const int kb = pi * KC;
        {
            const float* src = X + (size_t)(m0 + ar) * EMBED + kb + ac * 8;
            const uint32_t dst = sb + O3_A + pi * A3STG + ar * (LDW * 4) + ac * 32;
            cpa16(dst, src);
            cpa16(dst + 16, src + 4);
        }
        {
            const float* src = Wt + (size_t)br * EMBED + kb + bh * 16;
            const uint32_t dst = sb + O3_B + pi * B3STG + br * (LDW * 4) + bh * 64;
            #pragma unroll
            for (int j = 0; j < 4; ++j) cpa16(dst + j * 16, src + j * 4);
        }
        CP_COMMIT();
    }

    for (int kt = 0; kt < EMBED / KC; ++kt) {
        const int st = kt & 1;
        const uint32_t sA = sb + O3_A + st * A3STG;
        const uint32_t sB = sb + O3_B + st * B3STG;

        CP_WAIT1();
        __syncthreads();

        #pragma unroll
        for (int ks = 0; ks < 4; ++ks) {
            const int ko = ks * 16;
            uint32_t a[2][4], bb[2][4];
            #pragma unroll
            for (int mi = 0; mi < 2; ++mi)
                ldsm4(a[mi], sA + 2 * ((wm * 32 + mi * 16) * LDW16 + ko + aiA));
            #pragma unroll
            for (int h = 0; h < 2; ++h)
                ldsm4(bb[h], sB + 2 * ((wn * 32 + h * 16) * LDW16 + ko + biB));
            #pragma unroll
            for (int mi = 0; mi < 2; ++mi)
                #pragma unroll
                for (int nt = 0; nt < 4; ++nt)
                    mma1688t(c[mi][nt], a[mi], &bb[nt >> 1][(nt & 1) * 2]);
        }
        __syncthreads();

        if (kt + 2 < EMBED / KC) {
            const int kb = (kt + 2) * KC;
            {
                const float* src = X + (size_t)(m0 + ar) * EMBED + kb + ac * 8;
                const uint32_t dst = sb + O3_A + st * A3STG + ar * (LDW * 4) + ac * 32;
                cpa16(dst, src);
                cpa16(dst + 16, src + 4);
            }
            {
                const float* src = Wt + (size_t)br * EMBED + kb + bh * 16;
                const uint32_t dst = sb + O3_B + st * B3STG + br * (LDW * 4) + bh * 64;
                #pragma unroll
                for (int j = 0; j < 4; ++j) cpa16(dst + j * 16, src + j * 4);
            }
        }
        CP_COMMIT();
    }

    // ---- epilogue: frags (+bias) -> Ct -> bf16 hi/lo gmem
    __syncthreads();
    float (*Ct)[132] = (float (*)[132])smem;
    #pragma unroll
    for (int mi = 0; mi < 2; ++mi) {
        const int r = wm * 32 + mi * 16 + g;
        #pragma unroll
        for (int nt = 0; nt < 4; ++nt) {
            const int n = wn * 32 + nt * 8 + tig * 2;
            Ct[r][n]         = c[mi][nt][0] + biasS[n];
            Ct[r][n + 1]     = c[mi][nt][1] + biasS[n + 1];
            Ct[r + 8][n]     = c[mi][nt][2] + biasS[n];
            Ct[r + 8][n + 1] = c[mi][nt][3] + biasS[n + 1];
        }
    }
    __syncthreads();

    const int batch = m0 >> 11, s0 = m0 & 2047;
    if (wsel < 2) {
        const int r = t >> 2, dq = (t & 3) * 32;
        __nv_bfloat16* dhi = (wsel == 0 ? g_qhi : g_khi)
            + ((size_t)batch * SEQ + s0 + r) * HD + dq;
        __nv_bfloat16* dlo = (wsel == 0 ? g_qlo : g_klo)
            + ((size_t)batch * SEQ + s0 + r) * HD + dq;
        #pragma unroll
        for (int qq = 0; qq < 4; ++qq) {
            uint32_t hp[4], lp[4];
            #pragma unroll
            for (int e = 0; e < 4; ++e) {
                float x0 = Ct[r][dq + qq * 8 + e * 2];
                float x1 = Ct[r][dq + qq * 8 + e * 2 + 1];
                __nv_bfloat16 h0 = __float2bfloat16(x0);
                __nv_bfloat16 h1 = __float2bfloat16(x1);
                hp[e] = pk2(h0, h1);
                lp[e] = pk2(__float2bfloat16(x0 - __bfloat162float(h0)),
                            __float2bfloat16(x1 - __bfloat162float(h1)));
            }
            *(uint4*)(dhi + qq * 8) = make_uint4(hp[0], hp[1], hp[2], hp[3]);
            *(uint4*)(dlo + qq * 8) = make_uint4(lp[0], lp[1], lp[2], lp[3]);
        }
    } else {
        const int d = t >> 1, sch = (t & 1) * 32;
        size_t base = ((size_t)batch * HD + d) * SEQ + s0 + sch;
        #pragma unroll
        for (int qq = 0; qq < 4; ++qq) {
            uint32_t hp[4], lp[4];
            #pragma unroll
            for (int e = 0; e < 4; ++e) {
                float x0 = Ct[sch + qq * 8 + e * 2][d];
                float x1 = Ct[sch + qq * 8 + e * 2 + 1][d];
                __nv_bfloat16 h0 = __float2bfloat16(x0);
                __nv_bfloat16 h1 = __float2bfloat16(x1);
                hp[e] = pk2(h0, h1);
                lp[e] = pk2(__float2bfloat16(x0 - __bfloat162float(h0)),
                            __float2bfloat16(x1 - __bfloat162float(h1)));
            }
            *(uint4*)(g_vthi + base + qq * 8) = make_uint4(hp[0], hp[1], hp[2], hp[3]);
            *(uint4*)(g_vtlo + base + qq * 8) = make_uint4(lp[0], lp[1], lp[2], lp[3]);
        }
    }
}

// ---------------------------------------------------------------------------
// Attention v4 (R8-passing, bf16 3-term): cp.async 2-stage pipeline, 64-wide
// k-subtiles, balanced causal pairing. grid (32, 4).
// ---------------------------------------------------------------------------
#define KT   64
#define LDK  136
#define LDV  72
#define LDP  72
#define SPS  68

#define AO_QHI  0
#define AO_QLO  (AO_QHI + 32 * LDK * 2)
#define AO_KHI  (AO_QLO + 32 * LDK * 2)
#define AO_KLO  (AO_KHI + 2 * KT * LDK * 2)
#define AO_VHI  (AO_KLO + 2 * KT * LDK * 2)
#define AO_VLO  (AO_VHI + 2 * HD * LDV * 2)
#define AO_PS   (AO_VLO + 2 * HD * LDV * 2)
#define AO_PB   (AO_PS  + 32 * SPS * 4)
#define AO_PBL  (AO_PB  + 32 * LDP * 2)
#define AO_MLA  (AO_PBL + 32 * LDP * 2)
#define ASM_TOTAL (AO_MLA + 3 * 32 * 4)

__global__ __launch_bounds__(256)
void attn4(float* __restrict__ out)
{
    extern __shared__ char smem[];
    const uint32_t sb = smem_u32(smem);
    float* Ps   = (float*)(smem + AO_PS);
    float* m_s  = (float*)(smem + AO_MLA);
    float* l_s  = m_s + 32;
    float* al_s = l_s + 32;

    const int b = blockIdx.y, t = threadIdx.x;
    const int wid = t >> 5, lane = t & 31;
    const int g = lane >> 2, tig = lane & 3;
    const int wm = wid & 1, wn = wid >> 1;

    const int aiQ = (((lane >> 3) & 1) * 8 + (lane & 7)) * LDK + (lane >> 4) * 8;
    const int biK = ((lane >> 4) * 8 + (lane & 7)) * LDK + ((lane >> 3) & 1) * 8;
    const int aiP = (((lane >> 3) & 1) * 8 + (lane & 7)) * LDP + (lane >> 4) * 8;
    const int biV = ((lane >> 4) * 8 + (lane & 7)) * LDV + ((lane >> 3) & 1) * 8;

    const __nv_bfloat16* gQh = g_qhi + (size_t)b * SEQ * HD;
    const __nv_bfloat16* gQl = g_qlo + (size_t)b * SEQ * HD;
    const __nv_bfloat16* gKh = g_khi + (size_t)b * SEQ * HD;
    const __nv_bfloat16* gKl = g_klo + (size_t)b * SEQ * HD;
    const __nv_bfloat16* gVh = g_vthi + (size_t)b * HD * SEQ;
    const __nv_bfloat16* gVl = g_vtlo + (size_t)b * HD * SEQ;

    const float RSC = 0.08838834764831845f;
    const int sr = t >> 3, sc0 = (t & 7) * 8;
    const int kr = t >> 2, kq = t & 3;
    const int vr = t >> 1, vhh = t & 1;

    for (int subt = 0; subt < 2; ++subt) {
        const int jt = subt ? (63 - blockIdx.x) : blockIdx.x;
        const int q0 = jt * 32;
        const int iters = (jt >> 1) + 1;

        {
            const int r = t >> 3, dq = (t & 7) * 16;
            const __nv_bfloat16* sh = gQh + (size_t)(q0 + r) * HD + dq;
            const __nv_bfloat16* sl = gQl + (size_t)(q0 + r) * HD + dq;
            *(uint4*)(smem + AO_QHI + (r * LDK + dq) * 2)      = *(const uint4*)sh;
            *(uint4*)(smem + AO_QHI + (r * LDK + dq + 8) * 2)  = *(const uint4*)(sh + 8);
            *(uint4*)(smem + AO_QLO + (r * LDK + dq) * 2)      = *(const uint4*)sl;
            *(uint4*)(smem + AO_QLO + (r * LDK + dq + 8) * 2)  = *(const uint4*)(sl + 8);
        }
        if (t < 32) { m_s[t] = -1e30f; l_s[t] = 0.f; }

        float o[4][4];
        #pragma unroll
        for (int nt = 0; nt < 4; ++nt)
            #pragma unroll
            for (int q = 0; q < 4; ++q) o[nt][q] = 0.f;

        #pragma unroll
        for (int pi = 0; pi < 2; ++pi) {
            if (pi < iters) {
                const int k0 = pi * KT;
                const uint32_t kh_d = sb + AO_KHI + pi * (KT * LDK * 2) + kr * (LDK * 2) + kq * 64;
                const uint32_t kl_d = sb + AO_KLO + pi * (KT * LDK * 2) + kr * (LDK * 2) + kq * 64;
                const uint32_t vh_d = sb + AO_VHI + pi * (HD * LDV * 2) + vr * (LDV * 2) + vhh * 64;
                const uint32_t vl_d = sb + AO_VLO + pi * (HD * LDV * 2) + vr * (LDV * 2) + vhh * 64;
                const __nv_bfloat16* ksh = gKh + (size_t)(k0 + kr) * HD + kq * 32;
                const __nv_bfloat16* ksl = gKl + (size_t)(k0 + kr) * HD + kq * 32;
                const __nv_bfloat16* vsh = gVh + (size_t)vr * SEQ + k0 + vhh * 32;
                const __nv_bfloat16* vsl = gVl + (size_t)vr * SEQ + k0 + vhh * 32;
                #pragma unroll
                for (int j = 0; j < 4; ++j) {
                    cpa16(kh_d + j * 16, ksh + j * 8);
                    cpa16(kl_d + j * 16, ksl + j * 8);
                    cpa16(vh_d + j * 16, vsh + j * 8);
                    cpa16(vl_d + j * 16, vsl + j * 8);
                }
            }
            CP_COMMIT();
        }

        for (int it = 0; it < iters; ++it) {
            const int k0 = it * KT;
            const int st = it & 1;
            const uint32_t sKhi = sb + AO_KHI + st * (KT * LDK * 2);
            const uint32_t sKlo = sb + AO_KLO + st * (KT * LDK * 2);
            const uint32_t sVhi = sb + AO_VHI + st * (HD * LDV * 2);
            const uint32_t sVlo = sb + AO_VLO + st * (HD * LDV * 2);

            CP_WAIT1();
            __syncthreads();

            float s4[2][4];
            #pragma unroll
            for (int nt = 0; nt < 2; ++nt)
                #pragma unroll
                for (int q = 0; q < 4; ++q) s4[nt][q] = 0.f;
            #pragma unroll
            for (int ks = 0; ks < 8; ++ks) {
                const int k0s = ks * 16;
                uint32_t qh[4], ql[4], kh[4], kl[4];
                const uint32_t ao = 2 * (wm * 16 * LDK + k0s + aiQ);
                ldsm4(qh, sb + AO_QHI + ao);
                ldsm4(ql, sb + AO_QLO + ao);
                const uint32_t bo = 2 * (wn * 16 * LDK + k0s + biK);
                ldsm4(kh, sKhi + bo);
                ldsm4(kl, sKlo + bo);
                #pragma unroll
                for (int nt = 0; nt < 2; ++nt) {
                    mma16816(s4[nt], qh, &kh[nt * 2]);
                    mma16816(s4[nt], qh, &kl[nt * 2]);
                    mma16816(s4[nt], ql, &kh[nt * 2]);
                }
            }
            {
                const int row0 = wm * 16 + g;
                #pragma unroll
                for (int nt = 0; nt < 2; ++nt) {
                    const int col = wn * 16 + nt * 8 + tig * 2;
                    *(float2*)&Ps[row0 * SPS + col] = make_float2(s4[nt][0], s4[nt][1]);
                    *(float2*)&Ps[(row0 + 8) * SPS + col] = make_float2(s4[nt][2], s4[nt][3]);
                }
            }
            __syncthreads();

            {
                const int gq = q0 + sr;
                float sv[8];
                float rm = -1e30f;
                #pragma unroll
                for (int j = 0; j < 8; ++j) {
                    float v = Ps[sr * SPS + sc0 + j] * RSC;
                    if (k0 + sc0 + j > gq) v = -1e10f;
                    sv[j] = v;
                    rm = fmaxf(rm, v);
                }
                #pragma unroll
                for (int off = 4; off >= 1; off >>= 1)
                    rm = fmaxf(rm, __shfl_xor_sync(0xffffffffu, rm, off));
                const float mo = m_s[sr];
                const float mn = fmaxf(mo, rm);
                float rs = 0.f;
                uint32_t pph[4], ppl[4];
                #pragma unroll
                for (int j = 0; j < 4; ++j) {
                    float p0 = __expf(sv[2 * j] - mn);
                    float p1 = __expf(sv[2 * j + 1] - mn);
                    rs += p0 + p1;
                    __nv_bfloat16 h0 = __float2bfloat16(p0);
                    __nv_bfloat16 h1 = __float2bfloat16(p1);
                    pph[j] = pk2(h0, h1);
                    ppl[j] = pk2(__float2bfloat16(p0 - __bfloat162float(h0)),
                                 __float2bfloat16(p1 - __bfloat162float(h1)));
                }
                #pragma unroll
                for (int off = 4; off >= 1; off >>= 1)
                    rs += __shfl_xor_sync(0xffffffffu, rs, off);
                *(uint4*)(smem + AO_PB  + (sr * LDP + sc0) * 2) =
                    make_uint4(pph[0], pph[1], pph[2], pph[3]);
                *(uint4*)(smem + AO_PBL + (sr * LDP + sc0) * 2) =
                    make_uint4(ppl[0], ppl[1], ppl[2], ppl[3]);
                if ((t & 7) == 0) {
                    const float al = __expf(mo - mn);
                    m_s[sr]  = mn;
                    al_s[sr] = al;
                    l_s[sr]  = l_s[sr] * al + rs;
                }
            }
            __syncthreads();

            {
                const float a0 = al_s[wm * 16 + g];
                const float a1 = al_s[wm * 16 + g + 8];
                #pragma unroll
                for (int nt = 0; nt < 4; ++nt) {
                    o[nt][0] *= a0; o[nt][1] *= a0;
                    o[nt][2] *= a1; o[nt][3] *= a1;
                }
                #pragma unroll
                for (int ks = 0; ks < 4; ++ks) {
                    const int k0s = ks * 16;
                    uint32_t pa[4], pal[4], vh[2][4], vl[2][4];
                    const uint32_t po = 2 * (wm * 16 * LDP + k0s + aiP);
                    ldsm4(pa,  sb + AO_PB  + po);
                    ldsm4(pal, sb + AO_PBL + po);
                    #pragma unroll
                    for (int h = 0; h < 2; ++h) {
                        const uint32_t bo = 2 * ((wn * 32 + h * 16) * LDV + k0s + biV);
                        ldsm4(vh[h], sVhi + bo);
                        ldsm4(vl[h], sVlo + bo);
                    }
                    #pragma unroll
                    for (int nt = 0; nt < 4; ++nt) {
                        const uint32_t* vhp = &vh[nt >> 1][(nt & 1) * 2];
                        const uint32_t* vlp = &vl[nt >> 1][(nt & 1) * 2];
                        mma16816(o[nt], pa,  vhp);
                        mma16816(o[nt], pa,  vlp);
                        mma16816(o[nt], pal, vhp);
                    }
                }
            }
            __syncthreads();

            if (it + 2 < iters) {
                const int kn = (it + 2) * KT;
                const uint32_t kh_d = sb + AO_KHI + st * (KT * LDK * 2) + kr * (LDK * 2) + kq * 64;
                const uint32_t kl_d = sb + AO_KLO + st * (KT * LDK * 2) + kr * (LDK * 2) + kq * 64;
                const uint32_t vh_d = sb + AO_VHI + st * (HD * LDV * 2) + vr * (LDV * 2) + vhh * 64;
                const uint32_t vl_d = sb + AO_VLO + st * (HD * LDV * 2) + vr * (LDV * 2) + vhh * 64;
                const __nv_bfloat16* ksh = gKh + (size_t)(kn + kr) * HD + kq * 32;
                const __nv_bfloat16* ksl = gKl + (size_t)(kn + kr) * HD + kq * 32;
                const __nv_bfloat16* vsh = gVh + (size_t)vr * SEQ + kn + vhh * 32;
                const __nv_bfloat16* vsl = gVl + (size_t)vr * SEQ + kn + vhh * 32;
                #pragma unroll
                for (int j = 0; j < 4; ++j) {
                    cpa16(kh_d + j * 16, ksh + j * 8);
                    cpa16(kl_d + j * 16, ksl + j * 8);
                    cpa16(vh_d + j * 16, vsh + j * 8);
                    cpa16(vl_d + j * 16, vsl + j * 8);
                }
            }
            CP_COMMIT();
        }

        {
            const float li0 = 1.f / l_s[wm * 16 + g];
            const float li1 = 1.f / l_s[wm * 16 + g + 8];
            float* op0 = out + ((size_t)b * SEQ + q0 + wm * 16 + g) * HD;
            float* op1 = op0 + 8 * HD;
            #pragma unroll
            for (int nt = 0; nt < 4; ++nt) {
                const int d = wn * 32 + nt * 8 + tig * 2;
                *(float2*)(op0 + d) = make_float2(o[nt][0] * li0, o[nt][1] * li0);
                *(float2*)(op1 + d) = make_float2(o[nt][2] * li1, o[nt][3] * li1);
            }
        }
        __syncthreads();
    }
}

// ---------------------------------------------------------------------------
extern "C" void kernel_launch(void* const* d_in, const int* in_sizes, int n_in,
                              void* d_out, int out_size)
{
    const float* X  = (const float*)d_in[0];
    const float* Wq = (const float*)d_in[1];
    const float* bq = (const float*)d_in[2];
    const float* Wk = (const float*)d_in[3];
    const float* bk = (const float*)d_in[4];
    const float* Wv = (const float*)d_in[5];
    const float* bv = (const float*)d_in[6];
    float* out = (float*)d_out;

    prep_w48<<<48, 256>>>(Wq, Wk, Wv);

    cudaFuncSetAttribute(qkv3, cudaFuncAttributeMaxDynamicSharedMemorySize,
                         QSM3_TOTAL);
    qkv3<<<dim3(128, 3), 256, QSM3_TOTAL>>>(X, bq, bk, bv);

    cudaFuncSetAttribute(attn4, cudaFuncAttributeMaxDynamicSharedMemorySize,
                         ASM_TOTAL);
    attn4<<<dim3(32, 4), 256, ASM_TOTAL>>>(out);
}